// round 12
// baseline (speedup 1.0000x reference)
#include <cuda_runtime.h>

// ============================================================================
// 2-layer tanh RNN, B=32, L=2048, H=512 — v11: v10 + scout-warp sync offload.
//
// 128 persistent CTAs (1/SM), 544 threads = 16 worker warps + 1 SCOUT warp:
//   CTA 0..63   : layer 0 (A), output cols [cta*8, cta*8+8)
//   CTA 64..127 : layer 1 (B), cols [(cta-64)*8, ...)
// Worker structure = v10: pair (wp, wp+8) rows 4wp..4wp+3, warp wp = K-half 0,
// wp+8 = K-half 1; weights in SMEM (lane-interleaved, conflict-free LDS.128);
// A's x-side u(t)=x(t)@Wi0 computed 4 steps ahead into a register queue and
// published EARLY.
//
// Sync v11 — scout warp (warp 16, lane 0):
//   continuously polls the 3 global flag series with round-robin cursors
//   (ld.acquire.gpu) and posts monotonic ready-counters sRdy[0..2] =
//   {AL, AH, B} completed-step counts into SMEM via st.release.cta.
//   Workers spin on sRdy with ld.acquire.cta (~30 cyc when posted) — the
//   L2 RTT of the gate check is now hidden behind worker compute, and the
//   BAR256 leader-release barriers are GONE.
// Publication is per-warp: low warp STGs its 32 outputs -> __syncwarp ->
// lane0 red.release.gpu.add. Flag targets: AL/AH = 256 (8 low warps x 32
// CTAs), B = 512 (8 x 64). Happens-before chain: producer release ->
// scout acquire -> SMEM release -> worker acquire -> __ldcg data reads.
//
// Dataflow: L0 h -> 8-slot global ring (reuse: rdyB >= t-7); L1 h -> d_out.
// fp32 packed fma.rn.f32x2, numerics identical to v2..v10.
// ============================================================================

#define BB 32
#define LL 2048
#define HH 512
#define GA 64
#define GB 64
#define NTHR 544

__device__ float g_ring[8 * BB * HH];   // layer-0 h ring, 8 slots, 512 KB
__device__ int   g_flagAL[LL];          // A cols [0,256)   step t done (tgt 256)
__device__ int   g_flagAH[LL];          // A cols [256,512) step t done (tgt 256)
__device__ int   g_flagB[LL];           // B step t done (tgt 512)

__device__ __forceinline__ int acq(const int* p) {
    int v;
    asm volatile("ld.acquire.gpu.global.b32 %0, [%1];" : "=r"(v) : "l"(p) : "memory");
    return v;
}
__device__ __forceinline__ void rel_add(int* p) {
    asm volatile("red.release.gpu.global.add.u32 [%0], %1;"
                 :: "l"(p), "r"(1u) : "memory");
}
// SMEM ready-counter ops (generic addressing into shared)
__device__ __forceinline__ void strel(int* p, int v) {
    asm volatile("st.release.cta.b32 [%0], %1;" :: "l"(p), "r"(v) : "memory");
}
__device__ __forceinline__ void swait(const int* p, int tgt) {
    int v;
    do {
        asm volatile("ld.acquire.cta.b32 %0, [%1];" : "=r"(v) : "l"(p) : "memory");
    } while (v < tgt);
}
#define BAR64(id)  asm volatile("bar.sync %0, 64;"  :: "r"(id) : "memory")

#define FMA2(d, a, w) asm volatile("fma.rn.f32x2 %0, %1, %2, %0;" \
                                   : "+l"(d) : "l"(a), "l"(w))

__device__ __forceinline__ unsigned long long pack2(float v) {
    unsigned long long r;
    asm("mov.b64 %0, {%1,%1};" : "=l"(r) : "f"(v));
    return r;
}

__global__ void zero_flags_kernel() {
    int i = blockIdx.x * blockDim.x + threadIdx.x;
    if (i < LL) { g_flagAL[i] = 0; g_flagAH[i] = 0; g_flagB[i] = 0; }
}

// Accumulate ONE K-half (hk = 0: k<256, hk = 1: k>=256) of one side into
// acc[16] (acc[b*4+q] packs cols (2q,2q+1) for row b0+b). 8 LDG.128 batched
// up front. Weights lane-interleaved: [(i4*4+e)*32+ln] = k = 128*i4+4*ln+e.
__device__ __forceinline__ void accum_half(
    unsigned long long acc[16],
    const ulonglong2* __restrict__ wA, const ulonglong2* __restrict__ wB,
    const float* __restrict__ p, long long stride, int b0, int ln,
    int hk, bool cg)
{
    float4 v[2][4];
    #pragma unroll
    for (int j = 0; j < 2; j++) {
        int i4 = 2 * hk + j;
        #pragma unroll
        for (int b = 0; b < 4; b++) {
            const float4* a = (const float4*)(p + (long long)(b0 + b) * stride
                                              + 128 * i4 + 4 * ln);
            v[j][b] = cg ? __ldcg(a) : *a;
        }
    }
    #pragma unroll
    for (int j = 0; j < 2; j++) {
        int i4 = 2 * hk + j;
        #pragma unroll
        for (int e = 0; e < 4; e++) {
            ulonglong2 a  = wA[(i4 * 4 + e) * 32 + ln];
            ulonglong2 bq = wB[(i4 * 4 + e) * 32 + ln];
            #pragma unroll
            for (int b = 0; b < 4; b++) {
                float xv = (e == 0) ? v[j][b].x : (e == 1) ? v[j][b].y
                         : (e == 2) ? v[j][b].z : v[j][b].w;
                unsigned long long xp = pack2(xv);
                FMA2(acc[b * 4 + 0], xp, a.x);
                FMA2(acc[b * 4 + 1], xp, a.y);
                FMA2(acc[b * 4 + 2], xp, bq.x);
                FMA2(acc[b * 4 + 3], xp, bq.y);
            }
        }
    }
}

// Per-warp transpose-reduce over the 32-lane K split.
__device__ __forceinline__ float reduce32(const unsigned long long acc[16],
                                          float* redw, int ln)
{
    #pragma unroll
    for (int i = 0; i < 16; i++) {
        float2 v = *reinterpret_cast<const float2*>(&acc[i]);
        int a = (i >> 2) * 8 + (i & 3) * 2;
        redw[ln * 33 + a]     = v.x;
        redw[ln * 33 + a + 1] = v.y;
    }
    __syncwarp();
    float s0 = 0.f, s1 = 0.f, s2 = 0.f, s3 = 0.f;
    #pragma unroll
    for (int a = 0; a < 32; a += 4) {
        s0 += redw[(a + 0) * 33 + ln];
        s1 += redw[(a + 1) * 33 + ln];
        s2 += redw[(a + 2) * 33 + ln];
        s3 += redw[(a + 3) * 33 + ln];
    }
    __syncwarp();
    return (s0 + s1) + (s2 + s3);
}

__global__ __launch_bounds__(NTHR, 1) void rnn_kernel(
    const float* __restrict__ x,   const float* __restrict__ h0in,
    const float* __restrict__ Wi,  const float* __restrict__ bi,
    const float* __restrict__ Wh,  const float* __restrict__ bh,
    float* __restrict__ out, int write_final)
{
    extern __shared__ float smem[];
    ulonglong2* sWiA = (ulonglong2*)smem;      // [512] Wi cols 0-3
    ulonglong2* sWiB = sWiA + HH;              // [512] Wi cols 4-7
    ulonglong2* sWhA = sWiB + HH;
    ulonglong2* sWhB = sWhA + HH;
    float*      red    = (float*)(sWhB + HH);  // [16 warps][32][33]
    float*      comb_h = red + 16 * 32 * 33;   // [2][256]
    float*      comb_u = comb_h + 2 * 256;     // [2][256]
    int*        sRdy   = (int*)(comb_u + 2 * 256);  // [3]: AL, AH, B done-counts

    const int  cta   = blockIdx.x;
    const bool isA   = (cta < GA);
    const int  layer = isA ? 0 : 1;
    const int  c0    = (isA ? cta : cta - GA) * 8;
    const int  tid   = threadIdx.x;
    const int  w     = tid >> 5;
    const int  ln    = tid & 31;

    // ---- stage weight slices once (all 17 warps help) ----
    {
        const float* wi_g = Wi + (size_t)layer * HH * HH + c0;
        const float* wh_g = Wh + (size_t)layer * HH * HH + c0;
        for (int k = tid; k < HH; k += NTHR) {
            int idx = ((k >> 7) * 4 + (k & 3)) * 32 + ((k >> 2) & 31);
            const ulonglong2* ri = (const ulonglong2*)(wi_g + (size_t)k * HH);
            const ulonglong2* rh = (const ulonglong2*)(wh_g + (size_t)k * HH);
            sWiA[idx] = ri[0];  sWiB[idx] = ri[1];
            sWhA[idx] = rh[0];  sWhB[idx] = rh[1];
        }
    }
    if (tid == 0) { sRdy[0] = 0; sRdy[1] = 0; sRdy[2] = 0; }
    __syncthreads();    // one-time; no CTA-wide barrier after this

    // ======================= SCOUT WARP =======================
    if (w == 16) {
        if (ln == 0) {
            int cAL = 0, cAH = 0, cB = 0;
            while ((cAL < LL) || (cAH < LL) || (cB < LL)) {
                if (cAL < LL && acq(&g_flagAL[cAL]) >= 256) {
                    do { cAL++; } while (cAL < LL && acq(&g_flagAL[cAL]) >= 256);
                    strel(&sRdy[0], cAL);
                }
                if (cAH < LL && acq(&g_flagAH[cAH]) >= 256) {
                    do { cAH++; } while (cAH < LL && acq(&g_flagAH[cAH]) >= 256);
                    strel(&sRdy[1], cAH);
                }
                if (cB < LL && acq(&g_flagB[cB]) >= 512) {
                    do { cB++; } while (cB < LL && acq(&g_flagB[cB]) >= 512);
                    strel(&sRdy[2], cB);
                }
            }
        }
        return;
    }

    // ======================= WORKERS (16 warps, = v10) =======================
    const int  hk    = w >> 3;          // 0 = low K-half, 1 = high K-half
    const int  wp    = w & 7;           // pair index / low-warp id
    const int  b0    = 4 * wp;
    const int   myb  = b0 + (ln >> 3);
    const int   myc  = c0 + (ln & 7);
    const float bias = bi[layer * HH + myc] + bh[layer * HH + myc];
    float* redw = red + w * (32 * 33);
    const int ci = wp * 32 + ln;

    if (isA) {
        // ----------------------- LAYER 0 -----------------------
        float uq0 = 0.f, uq1 = 0.f, uq2 = 0.f, uq3 = 0.f;

        #pragma unroll 1
        for (int tw = 0; tw < 4; tw++) {        // warm-up u(0..3)
            unsigned long long au[16];
            #pragma unroll
            for (int i = 0; i < 16; i++) au[i] = 0ull;
            accum_half(au, sWiA, sWiB, x + (long long)tw * HH,
                       (long long)LL * HH, b0, ln, hk, false);
            float pu = reduce32(au, redw, ln);
            if (hk) {
                comb_u[(tw & 1) * 256 + ci] = pu;
                BAR64(3 + wp);
            } else {
                BAR64(3 + wp);
                float uv = pu + comb_u[(tw & 1) * 256 + ci];
                if (tw == 0) uq0 = uv; else if (tw == 1) uq1 = uv;
                else if (tw == 2) uq2 = uv; else uq3 = uv;
            }
        }

        #pragma unroll 1
        for (int t = 0; t < LL; t++) {
            unsigned long long acc[16];
            #pragma unroll
            for (int i = 0; i < 16; i++) acc[i] = 0ull;
            if (t == 0) {
                accum_half(acc, sWhA, sWhB, h0in, HH, b0, ln, hk, false);
            } else {
                if (hk == 0) {
                    swait(&sRdy[0], t);                 // AL[t-1] done
                    if (t >= 8) swait(&sRdy[2], t - 7); // ring slot free
                } else {
                    swait(&sRdy[1], t);                 // AH[t-1] done
                }
                accum_half(acc, sWhA, sWhB,
                           g_ring + ((t - 1) & 7) * (BB * HH), HH, b0, ln, hk, true);
            }
            float psum = reduce32(acc, redw, ln);

            // combine, tanh(+u), PUBLISH EARLY (per-warp)
            if (hk) {
                comb_h[(t & 1) * 256 + ci] = psum;
                BAR64(3 + wp);
            } else {
                BAR64(3 + wp);
                float hval = tanhf(psum + comb_h[(t & 1) * 256 + ci]
                                   + uq0 + bias);
                g_ring[(t & 7) * (BB * HH) + myb * HH + myc] = hval;
                if (write_final && t == LL - 1)
                    out[(long long)BB * LL * HH + myb * HH + myc] = hval;
                __syncwarp();
                if (ln == 0) rel_add(cta < 32 ? &g_flagAL[t] : &g_flagAH[t]);
            }

            // x-side u(t+4), off the critical path
            float unew = 0.f;
            if (t + 4 < LL) {
                unsigned long long au[16];
                #pragma unroll
                for (int i = 0; i < 16; i++) au[i] = 0ull;
                accum_half(au, sWiA, sWiB, x + (long long)(t + 4) * HH,
                           (long long)LL * HH, b0, ln, hk, false);
                float pu = reduce32(au, redw, ln);
                if (hk) {
                    comb_u[(t & 1) * 256 + ci] = pu;
                    BAR64(3 + wp);
                } else {
                    BAR64(3 + wp);
                    unew = pu + comb_u[(t & 1) * 256 + ci];
                }
            }
            uq0 = uq1; uq1 = uq2; uq2 = uq3; uq3 = unew;
        }
    } else {
        // ----------------------- LAYER 1 -----------------------
        #pragma unroll 1
        for (int t = 0; t < LL; t++) {
            unsigned long long acc[16];
            #pragma unroll
            for (int i = 0; i < 16; i++) acc[i] = 0ull;

            // ring side FIRST (A publishes early -> gate usually open)
            if (hk == 0) swait(&sRdy[0], t + 1);   // AL[t] done
            else         swait(&sRdy[1], t + 1);   // AH[t] done
            accum_half(acc, sWiA, sWiB, g_ring + (t & 7) * (BB * HH),
                       HH, b0, ln, hk, true);

            // own h1 side (gated on B[t-1])
            if (t == 0) {
                accum_half(acc, sWhA, sWhB, h0in + BB * HH, HH, b0, ln, hk, false);
            } else {
                swait(&sRdy[2], t);                // B[t-1] done
                accum_half(acc, sWhA, sWhB, out + (long long)(t - 1) * HH,
                           (long long)LL * HH, b0, ln, hk, true);
            }

            float psum = reduce32(acc, redw, ln);
            if (hk) {
                comb_h[(t & 1) * 256 + ci] = psum;
                BAR64(3 + wp);
            } else {
                BAR64(3 + wp);
                float hval = tanhf(psum + comb_h[(t & 1) * 256 + ci] + bias);
                out[(long long)myb * LL * HH + (long long)t * HH + myc] = hval;
                if (write_final && t == LL - 1)
                    out[(long long)BB * LL * HH + BB * HH + myb * HH + myc] = hval;
                __syncwarp();
                if (ln == 0) rel_add(&g_flagB[t]);
            }
        }
    }
}

extern "C" void kernel_launch(void* const* d_in, const int* in_sizes, int n_in,
                              void* d_out, int out_size)
{
    const float* x  = (const float*)d_in[0];
    const float* h0 = (const float*)d_in[1];
    const float* Wi = (const float*)d_in[2];
    const float* bi = (const float*)d_in[3];
    const float* Wh = (const float*)d_in[4];
    const float* bh = (const float*)d_in[5];
    float* out = (float*)d_out;

    int write_final = (out_size >= BB * LL * HH + 2 * BB * HH) ? 1 : 0;

    size_t smem = (size_t)(4 * HH * 16)                    // weights 32 KB
                + (size_t)(16 * 32 * 33) * sizeof(float)   // red    ~66 KB
                + (size_t)(4 * 256) * sizeof(float)        // comb_h/u 4 KB
                + 64;                                      // sRdy
    cudaFuncSetAttribute(rnn_kernel,
                         cudaFuncAttributeMaxDynamicSharedMemorySize, (int)smem);

    zero_flags_kernel<<<(LL + 255) / 256, 256>>>();
    rnn_kernel<<<GA + GB, NTHR, smem>>>(x, h0, Wi, bi, Wh, bh, out, write_final);
}

// round 13
// speedup vs baseline: 1.2024x; 1.2024x over previous
#include <cuda_runtime.h>

// ============================================================================
// 2-layer tanh RNN, B=32, L=2048, H=512 — v12: side-specialized warps.
//
// 128 persistent CTAs (1/SM), 512 threads (16 warps):
//   CTA 0..63   : layer 0 (A), output cols [cta*8, cta*8+8)
//   CTA 64..127 : layer 1 (B), cols [(cta-64)*8, ...)
//
// v12 change — warps split by GEMM SIDE, not K-half:
//   warps 0..7  (EARLY): A = x-side (UNGATED: always runnable);
//                        B = ring-side (gated on A's flags — arrive early)
//   warps 8..15 (LATE):  A = h-side + publish; B = h1-side + publish
//   Pair (wp, wp+8) covers rows 4wp..4wp+3. Early and late warps stall at
//   DIFFERENT times -> every SMSP always has issuable work (convoy broken).
//   Each warp does full-K for its side (accum_both: 16 batched LDG.128,
//   256 FMA2/thread); totals per CTA unchanged from v10.
//
// Combine: early writes comb[(t&1)]; BAR64(3+wp); late reads, adds its own
// reduced sum + bias, tanh, publishes. Publish: STG -> BAR256(2) (late half)
// -> warp8.lane0 red.release.gpu.add.
// Flags (v10 values): flagAL/AH[t] (A col-halves, tgt 32), flagB[t] (tgt 64).
// Gates: A-late: AL[t-1] & AH[t-1] & (t>=8) flagB[t-8] (ring reuse; flagB[t]
//   implies B ring-warps finished reading ring[t] via the BAR64 ordering).
//   B-early: AL[t] & AH[t].   B-late: flagB[t-1].
// Leader-warp polls (w8 for late half, w0 for B-early) + half-CTA barrier.
// Dataflow: L0 h -> 8-slot global ring; L1 h -> d_out. __ldcg cross-SM reads.
// fp32 packed fma.rn.f32x2, numerics identical to v2..v11.
// ============================================================================

#define BB 32
#define LL 2048
#define HH 512
#define GA 64
#define GB 64
#define NTHR 512

__device__ float g_ring[8 * BB * HH];   // layer-0 h ring, 8 slots, 512 KB
__device__ int   g_flagAL[LL];          // A cols [0,256)   done at t (tgt 32)
__device__ int   g_flagAH[LL];          // A cols [256,512) done at t (tgt 32)
__device__ int   g_flagB[LL];           // B done at t (tgt 64)

__device__ __forceinline__ int acq(const int* p) {
    int v;
    asm volatile("ld.acquire.gpu.global.b32 %0, [%1];" : "=r"(v) : "l"(p) : "memory");
    return v;
}
__device__ __forceinline__ void rel_add(int* p) {
    asm volatile("red.release.gpu.global.add.u32 [%0], %1;"
                 :: "l"(p), "r"(1u) : "memory");
}
#define BAR256(id) asm volatile("bar.sync %0, 256;" :: "r"(id) : "memory")
#define BAR64(id)  asm volatile("bar.sync %0, 64;"  :: "r"(id) : "memory")

#define FMA2(d, a, w) asm volatile("fma.rn.f32x2 %0, %1, %2, %0;" \
                                   : "+l"(d) : "l"(a), "l"(w))

__device__ __forceinline__ unsigned long long pack2(float v) {
    unsigned long long r;
    asm("mov.b64 %0, {%1,%1};" : "=l"(r) : "f"(v));
    return r;
}

__global__ void zero_flags_kernel() {
    int i = blockIdx.x * blockDim.x + threadIdx.x;
    if (i < LL) { g_flagAL[i] = 0; g_flagAH[i] = 0; g_flagB[i] = 0; }
}

// Full-K accumulation of ONE side: all 16 LDG.128 batched up front (MLP=16).
// acc[b*4+q] packs cols (2q,2q+1) for row b0+b. Weights lane-interleaved:
// [(i4*4+e)*32+ln] = k = 128*i4 + 4*ln + e.
__device__ __forceinline__ void accum_both(
    unsigned long long acc[16],
    const ulonglong2* __restrict__ wA, const ulonglong2* __restrict__ wB,
    const float* __restrict__ p, long long stride, int b0, int ln, bool cg)
{
    float4 v[4][4];   // [i4][b]
    #pragma unroll
    for (int i4 = 0; i4 < 4; i4++)
        #pragma unroll
        for (int b = 0; b < 4; b++) {
            const float4* a = (const float4*)(p + (long long)(b0 + b) * stride
                                              + 128 * i4 + 4 * ln);
            v[i4][b] = cg ? __ldcg(a) : *a;
        }
    #pragma unroll
    for (int i4 = 0; i4 < 4; i4++)
        #pragma unroll
        for (int e = 0; e < 4; e++) {
            ulonglong2 a  = wA[(i4 * 4 + e) * 32 + ln];
            ulonglong2 bq = wB[(i4 * 4 + e) * 32 + ln];
            #pragma unroll
            for (int b = 0; b < 4; b++) {
                float xv = (e == 0) ? v[i4][b].x : (e == 1) ? v[i4][b].y
                         : (e == 2) ? v[i4][b].z : v[i4][b].w;
                unsigned long long xp = pack2(xv);
                FMA2(acc[b * 4 + 0], xp, a.x);
                FMA2(acc[b * 4 + 1], xp, a.y);
                FMA2(acc[b * 4 + 2], xp, bq.x);
                FMA2(acc[b * 4 + 3], xp, bq.y);
            }
        }
}

// Per-warp transpose-reduce over the 32-lane K split.
__device__ __forceinline__ float reduce32(const unsigned long long acc[16],
                                          float* redw, int ln)
{
    #pragma unroll
    for (int i = 0; i < 16; i++) {
        float2 v = *reinterpret_cast<const float2*>(&acc[i]);
        int a = (i >> 2) * 8 + (i & 3) * 2;
        redw[ln * 33 + a]     = v.x;
        redw[ln * 33 + a + 1] = v.y;
    }
    __syncwarp();
    float s0 = 0.f, s1 = 0.f, s2 = 0.f, s3 = 0.f;
    #pragma unroll
    for (int a = 0; a < 32; a += 4) {
        s0 += redw[(a + 0) * 33 + ln];
        s1 += redw[(a + 1) * 33 + ln];
        s2 += redw[(a + 2) * 33 + ln];
        s3 += redw[(a + 3) * 33 + ln];
    }
    __syncwarp();
    return (s0 + s1) + (s2 + s3);
}

__global__ __launch_bounds__(NTHR, 1) void rnn_kernel(
    const float* __restrict__ x,   const float* __restrict__ h0in,
    const float* __restrict__ Wi,  const float* __restrict__ bi,
    const float* __restrict__ Wh,  const float* __restrict__ bh,
    float* __restrict__ out, int write_final)
{
    extern __shared__ float smem[];
    ulonglong2* sWiA = (ulonglong2*)smem;      // [512] Wi cols 0-3
    ulonglong2* sWiB = sWiA + HH;              // [512] Wi cols 4-7
    ulonglong2* sWhA = sWiB + HH;              // [512] Wh cols 0-3
    ulonglong2* sWhB = sWhA + HH;              // [512] Wh cols 4-7
    float*      red  = (float*)(sWhB + HH);    // [16 warps][32][33]
    float*      comb = red + 16 * 32 * 33;     // [2][256] early->late combine

    const int  cta   = blockIdx.x;
    const bool isA   = (cta < GA);
    const int  layer = isA ? 0 : 1;
    const int  c0    = (isA ? cta : cta - GA) * 8;
    const int  tid   = threadIdx.x;
    const int  w     = tid >> 5;
    const int  ln    = tid & 31;
    const int  late  = w >> 3;          // 0 = early side, 1 = late (critical)
    const int  wp    = w & 7;           // pair index
    const int  b0    = 4 * wp;

    // ---- stage weight slices once: idx(k) = ((k>>7)*4 + (k&3))*32 + ((k>>2)&31)
    {
        const float* wi_g = Wi + (size_t)layer * HH * HH + c0;
        const float* wh_g = Wh + (size_t)layer * HH * HH + c0;
        for (int k = tid; k < HH; k += NTHR) {
            int idx = ((k >> 7) * 4 + (k & 3)) * 32 + ((k >> 2) & 31);
            const ulonglong2* ri = (const ulonglong2*)(wi_g + (size_t)k * HH);
            const ulonglong2* rh = (const ulonglong2*)(wh_g + (size_t)k * HH);
            sWiA[idx] = ri[0];  sWiB[idx] = ri[1];
            sWhA[idx] = rh[0];  sWhB[idx] = rh[1];
        }
    }
    __syncthreads();    // one-time; no CTA-wide barrier in the loop

    const int   myb  = b0 + (ln >> 3);
    const int   myc  = c0 + (ln & 7);
    const float bias = bi[layer * HH + myc] + bh[layer * HH + myc];
    float* redw = red + w * (32 * 33);
    const int ci = wp * 32 + ln;

    if (isA) {
        if (!late) {
            // ========== A EARLY warps: x-side, UNGATED (always runnable) ====
            #pragma unroll 1
            for (int t = 0; t < LL; t++) {
                unsigned long long acc[16];
                #pragma unroll
                for (int i = 0; i < 16; i++) acc[i] = 0ull;
                accum_both(acc, sWiA, sWiB, x + (long long)t * HH,
                           (long long)LL * HH, b0, ln, false);
                comb[(t & 1) * 256 + ci] = reduce32(acc, redw, ln);
                BAR64(3 + wp);
            }
        } else {
            // ========== A LATE warps: h-side + publish (critical chain) =====
            #pragma unroll 1
            for (int t = 0; t < LL; t++) {
                unsigned long long acc[16];
                #pragma unroll
                for (int i = 0; i < 16; i++) acc[i] = 0ull;
                if (t == 0) {
                    accum_both(acc, sWhA, sWhB, h0in, HH, b0, ln, false);
                } else {
                    if (w == 8) {
                        if (t >= 8) { while (acq(&g_flagAL[t-1]) < 32 ||
                                             acq(&g_flagAH[t-1]) < 32 ||
                                             acq(&g_flagB[t-8])  < GB) {} }
                        else        { while (acq(&g_flagAL[t-1]) < 32 ||
                                             acq(&g_flagAH[t-1]) < 32) {} }
                    }
                    BAR256(2);
                    accum_both(acc, sWhA, sWhB,
                               g_ring + ((t - 1) & 7) * (BB * HH),
                               HH, b0, ln, true);
                }
                float psum = reduce32(acc, redw, ln);
                BAR64(3 + wp);   // x-side partial ready in comb
                float hval = tanhf(psum + comb[(t & 1) * 256 + ci] + bias);
                g_ring[(t & 7) * (BB * HH) + myb * HH + myc] = hval;
                if (write_final && t == LL - 1)
                    out[(long long)BB * LL * HH + myb * HH + myc] = hval;
                BAR256(2);       // all late STGs issued
                if (w == 8 && ln == 0)
                    rel_add(cta < 32 ? &g_flagAL[t] : &g_flagAH[t]);
            }
        }
    } else {
        if (!late) {
            // ========== B EARLY warps: ring-side (gated on A, arrives early) =
            #pragma unroll 1
            for (int t = 0; t < LL; t++) {
                unsigned long long acc[16];
                #pragma unroll
                for (int i = 0; i < 16; i++) acc[i] = 0ull;
                if (w == 0) { while (acq(&g_flagAL[t]) < 32 ||
                                     acq(&g_flagAH[t]) < 32) {} }
                BAR256(1);
                accum_both(acc, sWiA, sWiB, g_ring + (t & 7) * (BB * HH),
                           HH, b0, ln, true);
                comb[(t & 1) * 256 + ci] = reduce32(acc, redw, ln);
                BAR64(3 + wp);
            }
        } else {
            // ========== B LATE warps: h1-side + publish (critical chain) ====
            #pragma unroll 1
            for (int t = 0; t < LL; t++) {
                unsigned long long acc[16];
                #pragma unroll
                for (int i = 0; i < 16; i++) acc[i] = 0ull;
                if (t == 0) {
                    accum_both(acc, sWhA, sWhB, h0in + BB * HH,
                               HH, b0, ln, false);
                } else {
                    if (w == 8) { while (acq(&g_flagB[t-1]) < GB) {} }
                    BAR256(2);
                    accum_both(acc, sWhA, sWhB, out + (long long)(t - 1) * HH,
                               (long long)LL * HH, b0, ln, true);
                }
                float psum = reduce32(acc, redw, ln);
                BAR64(3 + wp);   // ring-side partial ready in comb
                float hval = tanhf(psum + comb[(t & 1) * 256 + ci] + bias);
                out[(long long)myb * LL * HH + (long long)t * HH + myc] = hval;
                if (write_final && t == LL - 1)
                    out[(long long)BB * LL * HH + BB * HH + myb * HH + myc] = hval;
                BAR256(2);       // all late STGs issued
                if (w == 8 && ln == 0) rel_add(&g_flagB[t]);
            }
        }
    }
}

extern "C" void kernel_launch(void* const* d_in, const int* in_sizes, int n_in,
                              void* d_out, int out_size)
{
    const float* x  = (const float*)d_in[0];
    const float* h0 = (const float*)d_in[1];
    const float* Wi = (const float*)d_in[2];
    const float* bi = (const float*)d_in[3];
    const float* Wh = (const float*)d_in[4];
    const float* bh = (const float*)d_in[5];
    float* out = (float*)d_out;

    int write_final = (out_size >= BB * LL * HH + 2 * BB * HH) ? 1 : 0;

    size_t smem = (size_t)(4 * HH * 16)                    // weights 32 KB
                + (size_t)(16 * 32 * 33) * sizeof(float)   // red    ~66 KB
                + (size_t)(2 * 256) * sizeof(float);       // comb     2 KB
    cudaFuncSetAttribute(rnn_kernel,
                         cudaFuncAttributeMaxDynamicSharedMemorySize, (int)smem);

    zero_flags_kernel<<<(LL + 255) / 256, 256>>>();
    rnn_kernel<<<GA + GB, NTHR, smem>>>(x, h0, Wi, bi, Wh, bh, out, write_final);
}